// round 1
// baseline (speedup 1.0000x reference)
#include <cuda_runtime.h>
#include <math.h>

#define B_   2
#define N_   4096
#define IC_  256
#define PC_  128
#define OC_  128
#define SCALE_ 0.08838834764831845f   // 1/sqrt(128)

// ---------------- scratch (device globals; no allocation allowed) ----------
static __device__ float g_rp  [(size_t)B_ * N_ * PC_];   // point_features^T  [B,N,128]
static __device__ float g_ri  [(size_t)B_ * N_ * PC_];   // fc2(img^T)        [B,N,128]
static __device__ float g_S   [(size_t)B_ * N_ * N_];    // scores            [B,N,N] 134MB
static __device__ float g_cmax[B_ * N_];
static __device__ float g_cinv[B_ * N_];
static __device__ float g_rmax[B_ * N_];
static __device__ float g_rinv[B_ * N_];
static __device__ float g_outp[(size_t)B_ * N_ * PC_];
static __device__ float g_outi[(size_t)B_ * N_ * PC_];

__device__ __forceinline__ void sm_combine(float& m, float& s, float m2, float s2) {
    float nm = fmaxf(m, m2);
    s = s * __expf(m - nm) + s2 * __expf(m2 - nm);
    m = nm;
}

// ---------------- kernel 1: transpose point_features [B,PC,N] -> rp [B,N,PC]
__global__ void k_transpose(const float* __restrict__ pf) {
    __shared__ float tile[32][33];
    const int b  = blockIdx.z;
    const int n0 = blockIdx.x * 32;
    const int d0 = blockIdx.y * 32;
    const float* src = pf   + (size_t)b * PC_ * N_;
    float*       dst = g_rp + (size_t)b * N_ * PC_;
    const int tx = threadIdx.x, ty = threadIdx.y;   // (32, 8)
#pragma unroll
    for (int j = 0; j < 32; j += 8)
        tile[ty + j][tx] = src[(size_t)(d0 + ty + j) * N_ + n0 + tx];
    __syncthreads();
#pragma unroll
    for (int j = 0; j < 32; j += 8)
        dst[(size_t)(n0 + ty + j) * PC_ + d0 + tx] = tile[tx][ty + j];
}

// ---------------- kernel 2: ri = img^T @ fc2_w^T + fc2_b  (per batch: [N,256]@[256,128])
// tile: 64 n x 128 d, block 16x16, thread 4n x 8d, K chunk 16
__global__ void k_ri(const float* __restrict__ img, const float* __restrict__ w,
                     const float* __restrict__ bias) {
    const int b  = blockIdx.z;
    const int n0 = blockIdx.y * 64;
    const float* X = img  + (size_t)b * IC_ * N_;
    float*       R = g_ri + (size_t)b * N_ * PC_;
    __shared__ float As[16][64];
    __shared__ float Bs[16][128];
    const int tx = threadIdx.x, ty = threadIdx.y;
    const int tid = ty * 16 + tx;
    float acc[4][8];
#pragma unroll
    for (int i = 0; i < 4; i++)
#pragma unroll
        for (int j = 0; j < 8; j++) acc[i][j] = 0.f;

    for (int k0 = 0; k0 < IC_; k0 += 16) {
        { // As[kk][nn] = X[(k0+kk)*N + n0+nn]
            int l = tid * 4, kk = l / 64, nn = l % 64;
            float4 v = *(const float4*)&X[(size_t)(k0 + kk) * N_ + n0 + nn];
            *(float4*)&As[kk][nn] = v;
        }
        { // Bs[kk][dd] = w[dd*IC + k0+kk]
            int l = tid * 8, dd = l / 16, kk = l % 16;
            float4 v0 = *(const float4*)&w[(size_t)dd * IC_ + k0 + kk];
            float4 v1 = *(const float4*)&w[(size_t)dd * IC_ + k0 + kk + 4];
            Bs[kk + 0][dd] = v0.x; Bs[kk + 1][dd] = v0.y;
            Bs[kk + 2][dd] = v0.z; Bs[kk + 3][dd] = v0.w;
            Bs[kk + 4][dd] = v1.x; Bs[kk + 5][dd] = v1.y;
            Bs[kk + 6][dd] = v1.z; Bs[kk + 7][dd] = v1.w;
        }
        __syncthreads();
#pragma unroll
        for (int kk = 0; kk < 16; kk++) {
            float a[4], bb[8];
#pragma unroll
            for (int i = 0; i < 4; i++) a[i] = As[kk][ty * 4 + i];
#pragma unroll
            for (int j = 0; j < 8; j++) bb[j] = Bs[kk][tx * 8 + j];
#pragma unroll
            for (int i = 0; i < 4; i++)
#pragma unroll
                for (int j = 0; j < 8; j++) acc[i][j] += a[i] * bb[j];
        }
        __syncthreads();
    }
#pragma unroll
    for (int i = 0; i < 4; i++) {
        int n = n0 + ty * 4 + i;
#pragma unroll
        for (int j = 0; j < 8; j++) {
            int d = tx * 8 + j;
            R[(size_t)n * PC_ + d] = acc[i][j] + bias[d];
        }
    }
}

// ---------------- kernel 3: S = scale * rp @ ri^T  (per batch [N,128]@[128,N])
// tile: 128 i x 64 j, block 16x16, thread 8i x 4j, K chunk 16
__global__ void k_s() {
    const int b  = blockIdx.z;
    const int i0 = blockIdx.y * 128;
    const int j0 = blockIdx.x * 64;
    const float* A  = g_rp + (size_t)b * N_ * PC_;
    const float* Bm = g_ri + (size_t)b * N_ * PC_;
    float*       Sp = g_S  + (size_t)b * N_ * N_;
    __shared__ float As[16][128];
    __shared__ float Bs[16][64];
    const int tx = threadIdx.x, ty = threadIdx.y;
    const int tid = ty * 16 + tx;
    float acc[8][4];
#pragma unroll
    for (int i = 0; i < 8; i++)
#pragma unroll
        for (int j = 0; j < 4; j++) acc[i][j] = 0.f;

    for (int k0 = 0; k0 < PC_; k0 += 16) {
        { // As[kk][ii] = A[(i0+ii)*PC + k0+kk]
            int l = tid * 8, ii = l / 16, kk = l % 16;
            float4 v0 = *(const float4*)&A[(size_t)(i0 + ii) * PC_ + k0 + kk];
            float4 v1 = *(const float4*)&A[(size_t)(i0 + ii) * PC_ + k0 + kk + 4];
            As[kk + 0][ii] = v0.x; As[kk + 1][ii] = v0.y;
            As[kk + 2][ii] = v0.z; As[kk + 3][ii] = v0.w;
            As[kk + 4][ii] = v1.x; As[kk + 5][ii] = v1.y;
            As[kk + 6][ii] = v1.z; As[kk + 7][ii] = v1.w;
        }
        { // Bs[kk][jj] = Bm[(j0+jj)*PC + k0+kk]
            int l = tid * 4, jj = l / 16, kk = l % 16;
            float4 v = *(const float4*)&Bm[(size_t)(j0 + jj) * PC_ + k0 + kk];
            Bs[kk + 0][jj] = v.x; Bs[kk + 1][jj] = v.y;
            Bs[kk + 2][jj] = v.z; Bs[kk + 3][jj] = v.w;
        }
        __syncthreads();
#pragma unroll
        for (int kk = 0; kk < 16; kk++) {
            float a[8], bb[4];
#pragma unroll
            for (int i = 0; i < 8; i++) a[i] = As[kk][ty * 8 + i];
#pragma unroll
            for (int j = 0; j < 4; j++) bb[j] = Bs[kk][tx * 4 + j];
#pragma unroll
            for (int i = 0; i < 8; i++)
#pragma unroll
                for (int j = 0; j < 4; j++) acc[i][j] += a[i] * bb[j];
        }
        __syncthreads();
    }
#pragma unroll
    for (int i = 0; i < 8; i++) {
        int ii = i0 + ty * 8 + i;
        float4 v = make_float4(acc[i][0] * SCALE_, acc[i][1] * SCALE_,
                               acc[i][2] * SCALE_, acc[i][3] * SCALE_);
        *(float4*)&Sp[(size_t)ii * N_ + j0 + tx * 4] = v;
    }
}

// ---------------- kernel 4: column stats (softmax over axis i, per column j)
__global__ void k_colstats() {
    const int b = blockIdx.y;
    const int j = blockIdx.x * 32 + threadIdx.x;
    const float* Sp = g_S + (size_t)b * N_ * N_;
    float m = -1e30f, s = 0.f;
    for (int i = threadIdx.y; i < N_; i += 16) {
        float x  = Sp[(size_t)i * N_ + j];
        float nm = fmaxf(m, x);
        s = s * __expf(m - nm) + __expf(x - nm);
        m = nm;
    }
    __shared__ float sm[16][32], ss[16][32];
    sm[threadIdx.y][threadIdx.x] = m;
    ss[threadIdx.y][threadIdx.x] = s;
    __syncthreads();
    if (threadIdx.y == 0) {
#pragma unroll
        for (int t = 1; t < 16; t++)
            sm_combine(m, s, sm[t][threadIdx.x], ss[t][threadIdx.x]);
        g_cmax[b * N_ + j] = m;
        g_cinv[b * N_ + j] = 1.0f / s;
    }
}

// ---------------- kernel 5: row stats (softmax over axis j, per row i)
__global__ void k_rowstats() {
    const int b = blockIdx.y;
    const int i = blockIdx.x;
    const float* row = g_S + (size_t)b * N_ * N_ + (size_t)i * N_;
    float m = -1e30f, s = 0.f;
    for (int j = threadIdx.x; j < N_; j += 256) {
        float x  = row[j];
        float nm = fmaxf(m, x);
        s = s * __expf(m - nm) + __expf(x - nm);
        m = nm;
    }
#pragma unroll
    for (int off = 16; off; off >>= 1) {
        float om = __shfl_xor_sync(0xffffffffu, m, off);
        float os = __shfl_xor_sync(0xffffffffu, s, off);
        sm_combine(m, s, om, os);
    }
    __shared__ float sm[8], ss[8];
    const int lane = threadIdx.x & 31, wid = threadIdx.x >> 5;
    if (lane == 0) { sm[wid] = m; ss[wid] = s; }
    __syncthreads();
    if (threadIdx.x == 0) {
#pragma unroll
        for (int t = 1; t < 8; t++) sm_combine(m, s, sm[t], ss[t]);
        g_rmax[b * N_ + i] = m;
        g_rinv[b * N_ + i] = 1.0f / s;
    }
}

// ---------------- kernel 6: fused attention-value GEMMs.
// mode 0: out_p[i,d] = sum_j exp(S[i,j]-cmax[j])*cinv[j]*rp[j,d]
// mode 1: out_i[i,d] = sum_j exp(S[j,i]-rmax[j])*rinv[j]*ri[j,d]
// tile: 64 i x 128 d, block 16x16, thread 4i x 8d, K chunk 16, K = 4096
__global__ void k_av() {
    const int mode = blockIdx.x;            // 0 or 1
    const int b    = blockIdx.z;
    const int i0   = blockIdx.y * 64;
    const float* Sp = g_S + (size_t)b * N_ * N_;
    const float* Bm = (mode == 0 ? g_rp : g_ri) + (size_t)b * N_ * PC_;
    const float* mx = (mode == 0 ? g_cmax : g_rmax) + b * N_;
    const float* iv = (mode == 0 ? g_cinv : g_rinv) + b * N_;
    float*       D  = (mode == 0 ? g_outp : g_outi) + (size_t)b * N_ * PC_;

    __shared__ float As[16][64];
    __shared__ float Bs[16][128];
    const int tx = threadIdx.x, ty = threadIdx.y;
    const int tid = ty * 16 + tx;
    float acc[4][8];
#pragma unroll
    for (int i = 0; i < 4; i++)
#pragma unroll
        for (int j = 0; j < 8; j++) acc[i][j] = 0.f;

    for (int k0 = 0; k0 < N_; k0 += 16) {
        if (mode == 0) {       // As[kk][ii] = exp(S[i0+ii][k0+kk] - cmax[k0+kk])
            int l = tid * 4, ii = l / 16, kk = l % 16;
            float4 v  = *(const float4*)&Sp[(size_t)(i0 + ii) * N_ + k0 + kk];
            float4 cm = *(const float4*)&mx[k0 + kk];
            As[kk + 0][ii] = __expf(v.x - cm.x);
            As[kk + 1][ii] = __expf(v.y - cm.y);
            As[kk + 2][ii] = __expf(v.z - cm.z);
            As[kk + 3][ii] = __expf(v.w - cm.w);
        } else {               // As[kk][ii] = exp(S[k0+kk][i0+ii] - rmax[k0+kk])
            int l = tid * 4, kk = l / 64, ii = l % 64;
            float4 v = *(const float4*)&Sp[(size_t)(k0 + kk) * N_ + i0 + ii];
            float  r = mx[k0 + kk];
            float4 o = make_float4(__expf(v.x - r), __expf(v.y - r),
                                   __expf(v.z - r), __expf(v.w - r));
            *(float4*)&As[kk][ii] = o;
        }
        { // Bs[kk][dd] = Bm[(k0+kk)*PC + dd] * inv[k0+kk]
            int l = tid * 8, kk = l / 128, dd = l % 128;
            float  cs = iv[k0 + kk];
            float4 v0 = *(const float4*)&Bm[(size_t)(k0 + kk) * PC_ + dd];
            float4 v1 = *(const float4*)&Bm[(size_t)(k0 + kk) * PC_ + dd + 4];
            v0.x *= cs; v0.y *= cs; v0.z *= cs; v0.w *= cs;
            v1.x *= cs; v1.y *= cs; v1.z *= cs; v1.w *= cs;
            *(float4*)&Bs[kk][dd]     = v0;
            *(float4*)&Bs[kk][dd + 4] = v1;
        }
        __syncthreads();
#pragma unroll
        for (int kk = 0; kk < 16; kk++) {
            float a[4], bb[8];
#pragma unroll
            for (int i = 0; i < 4; i++) a[i] = As[kk][ty * 4 + i];
#pragma unroll
            for (int j = 0; j < 8; j++) bb[j] = Bs[kk][tx * 8 + j];
#pragma unroll
            for (int i = 0; i < 4; i++)
#pragma unroll
                for (int j = 0; j < 8; j++) acc[i][j] += a[i] * bb[j];
        }
        __syncthreads();
    }
#pragma unroll
    for (int i = 0; i < 4; i++) {
        int ii = i0 + ty * 4 + i;
        float4 v0 = make_float4(acc[i][0], acc[i][1], acc[i][2], acc[i][3]);
        float4 v1 = make_float4(acc[i][4], acc[i][5], acc[i][6], acc[i][7]);
        *(float4*)&D[(size_t)ii * PC_ + tx * 8]     = v0;
        *(float4*)&D[(size_t)ii * PC_ + tx * 8 + 4] = v1;
    }
}

// ---------------- kernel 7: conv1d(k=1) + BN(eval) + ReLU
// y[b,o,n] = relu(g[o]*(sum_c w[o,c]*fusion[c,n] + conv_b[o] - mean[o]) + beta[o])
// fusion[c,n] = c<128 ? out_p[n,c] : out_i[n,c-128]
// tile: 128 o x 64 n, block 16x16, thread 8o x 4n, K = 256 chunk 16
__global__ void k_conv(const float* __restrict__ w,     const float* __restrict__ cb,
                       const float* __restrict__ gamma, const float* __restrict__ beta,
                       const float* __restrict__ mean,  const float* __restrict__ var,
                       float* __restrict__ out) {
    const int b  = blockIdx.z;
    const int n0 = blockIdx.x * 64;
    const float* P = g_outp + (size_t)b * N_ * PC_;
    const float* I = g_outi + (size_t)b * N_ * PC_;
    __shared__ float As[16][128];
    __shared__ float Bs[16][64];
    const int tx = threadIdx.x, ty = threadIdx.y;
    const int tid = ty * 16 + tx;
    float acc[8][4];
#pragma unroll
    for (int i = 0; i < 8; i++)
#pragma unroll
        for (int j = 0; j < 4; j++) acc[i][j] = 0.f;

    for (int k0 = 0; k0 < 2 * PC_; k0 += 16) {
        { // As[kk][oo] = w[oo*256 + k0+kk]
            int l = tid * 8, oo = l / 16, kk = l % 16;
            float4 v0 = *(const float4*)&w[(size_t)oo * (2 * PC_) + k0 + kk];
            float4 v1 = *(const float4*)&w[(size_t)oo * (2 * PC_) + k0 + kk + 4];
            As[kk + 0][oo] = v0.x; As[kk + 1][oo] = v0.y;
            As[kk + 2][oo] = v0.z; As[kk + 3][oo] = v0.w;
            As[kk + 4][oo] = v1.x; As[kk + 5][oo] = v1.y;
            As[kk + 6][oo] = v1.z; As[kk + 7][oo] = v1.w;
        }
        { // Bs[kk][nn] = fusion[k0+kk][n0+nn]
            int l = tid * 4, nn = l / 16, kk = l % 16;
            const float* src = (k0 < PC_) ? &P[(size_t)(n0 + nn) * PC_ + k0 + kk]
                                          : &I[(size_t)(n0 + nn) * PC_ + k0 - PC_ + kk];
            float4 v = *(const float4*)src;
            Bs[kk + 0][nn] = v.x; Bs[kk + 1][nn] = v.y;
            Bs[kk + 2][nn] = v.z; Bs[kk + 3][nn] = v.w;
        }
        __syncthreads();
#pragma unroll
        for (int kk = 0; kk < 16; kk++) {
            float a[8], bb[4];
#pragma unroll
            for (int i = 0; i < 8; i++) a[i] = As[kk][ty * 8 + i];
#pragma unroll
            for (int j = 0; j < 4; j++) bb[j] = Bs[kk][tx * 4 + j];
#pragma unroll
            for (int i = 0; i < 8; i++)
#pragma unroll
                for (int j = 0; j < 4; j++) acc[i][j] += a[i] * bb[j];
        }
        __syncthreads();
    }
#pragma unroll
    for (int i = 0; i < 8; i++) {
        int o = ty * 8 + i;
        float g    = gamma[o] * rsqrtf(var[o] + 1e-5f);
        float base = g * (cb[o] - mean[o]) + beta[o];
        float4 v;
        v.x = fmaxf(g * acc[i][0] + base, 0.f);
        v.y = fmaxf(g * acc[i][1] + base, 0.f);
        v.z = fmaxf(g * acc[i][2] + base, 0.f);
        v.w = fmaxf(g * acc[i][3] + base, 0.f);
        *(float4*)&out[(size_t)b * OC_ * N_ + (size_t)o * N_ + n0 + tx * 4] = v;
    }
}

// ---------------- launch -----------------------------------------------------
extern "C" void kernel_launch(void* const* d_in, const int* in_sizes, int n_in,
                              void* d_out, int out_size) {
    const float* pf     = (const float*)d_in[0];
    const float* img    = (const float*)d_in[1];
    const float* fc2_w  = (const float*)d_in[2];
    const float* fc2_b  = (const float*)d_in[3];
    const float* conv_w = (const float*)d_in[4];
    const float* conv_b = (const float*)d_in[5];
    const float* gamma  = (const float*)d_in[6];
    const float* beta   = (const float*)d_in[7];
    const float* mean   = (const float*)d_in[8];
    const float* var    = (const float*)d_in[9];
    float* out = (float*)d_out;

    k_transpose<<<dim3(N_ / 32, PC_ / 32, B_), dim3(32, 8)>>>(pf);
    k_ri       <<<dim3(1, N_ / 64, B_),        dim3(16, 16)>>>(img, fc2_w, fc2_b);
    k_s        <<<dim3(N_ / 64, N_ / 128, B_), dim3(16, 16)>>>();
    k_colstats <<<dim3(N_ / 32, B_),           dim3(32, 16)>>>();
    k_rowstats <<<dim3(N_, B_),                256>>>();
    k_av       <<<dim3(2, N_ / 64, B_),        dim3(16, 16)>>>();
    k_conv     <<<dim3(N_ / 64, 1, B_),        dim3(16, 16)>>>(conv_w, conv_b, gamma, beta,
                                                               mean, var, out);
}

// round 2
// speedup vs baseline: 2.0487x; 2.0487x over previous
#include <cuda_runtime.h>
#include <math.h>

#define B_   2
#define N_   4096
#define IC_  256
#define PC_  128
#define OC_  128
#define SCALE_ 0.08838834764831845f   // 1/sqrt(128)

// ---------------- scratch (device globals) ----------------------------------
static __device__ float g_rp  [(size_t)B_ * N_ * PC_];   // point_features^T [B,N,128]
static __device__ float g_ri  [(size_t)B_ * N_ * PC_];   // fc2(img^T)       [B,N,128]
static __device__ float g_S   [(size_t)B_ * N_ * N_];    // P = exp(scale*S) [B,N,N]
static __device__ float g_csum[B_ * N_];                 // sum_i P[i][j]
static __device__ float g_rsum[B_ * N_];                 // sum_j P[i][j]
static __device__ float g_outp[(size_t)B_ * N_ * PC_];
static __device__ float g_outi[(size_t)B_ * N_ * PC_];

// ---------------- mma helpers ------------------------------------------------
__device__ __forceinline__ unsigned tf32_of(float x) {
    unsigned r; asm("cvt.rna.tf32.f32 %0, %1;" : "=r"(r) : "f"(x)); return r;
}
__device__ __forceinline__ void mma_tf32(float* c, unsigned a0, unsigned a1,
                                         unsigned a2, unsigned a3,
                                         unsigned b0, unsigned b1) {
    asm volatile(
        "mma.sync.aligned.m16n8k8.row.col.f32.tf32.tf32.f32 "
        "{%0,%1,%2,%3}, {%4,%5,%6,%7}, {%8,%9}, {%0,%1,%2,%3};"
        : "+f"(c[0]), "+f"(c[1]), "+f"(c[2]), "+f"(c[3])
        : "r"(a0), "r"(a1), "r"(a2), "r"(a3), "r"(b0), "r"(b1));
}

#define LDM 136   // shared leading dim: (t*8+g) banks conflict-free for frag loads

// ---------------- kernel 0: zero the sum accumulators ------------------------
__global__ void k_zero() {
    int i = blockIdx.x * blockDim.x + threadIdx.x;
    if (i < B_ * N_) { g_csum[i] = 0.f; g_rsum[i] = 0.f; }
}

// ---------------- kernel 1: transpose point_features [B,PC,N] -> rp [B,N,PC]
__global__ void k_transpose(const float* __restrict__ pf) {
    __shared__ float tile[32][33];
    const int b  = blockIdx.z;
    const int n0 = blockIdx.x * 32;
    const int d0 = blockIdx.y * 32;
    const float* src = pf   + (size_t)b * PC_ * N_;
    float*       dst = g_rp + (size_t)b * N_ * PC_;
    const int tx = threadIdx.x, ty = threadIdx.y;   // (32, 8)
#pragma unroll
    for (int j = 0; j < 32; j += 8)
        tile[ty + j][tx] = src[(size_t)(d0 + ty + j) * N_ + n0 + tx];
    __syncthreads();
#pragma unroll
    for (int j = 0; j < 32; j += 8)
        dst[(size_t)(n0 + ty + j) * PC_ + d0 + tx] = tile[tx][ty + j];
}

// ---------------- kernel 2: ri = img^T @ fc2_w^T + fc2_b ---------------------
__global__ void k_ri(const float* __restrict__ img, const float* __restrict__ w,
                     const float* __restrict__ bias) {
    const int b  = blockIdx.z;
    const int n0 = blockIdx.y * 64;
    const float* X = img  + (size_t)b * IC_ * N_;
    float*       R = g_ri + (size_t)b * N_ * PC_;
    __shared__ float As[16][64];
    __shared__ float Bs[16][128];
    const int tx = threadIdx.x, ty = threadIdx.y;
    const int tid = ty * 16 + tx;
    float acc[4][8];
#pragma unroll
    for (int i = 0; i < 4; i++)
#pragma unroll
        for (int j = 0; j < 8; j++) acc[i][j] = 0.f;

    for (int k0 = 0; k0 < IC_; k0 += 16) {
        {
            int l = tid * 4, kk = l / 64, nn = l % 64;
            float4 v = *(const float4*)&X[(size_t)(k0 + kk) * N_ + n0 + nn];
            *(float4*)&As[kk][nn] = v;
        }
        {
            int l = tid * 8, dd = l / 16, kk = l % 16;
            float4 v0 = *(const float4*)&w[(size_t)dd * IC_ + k0 + kk];
            float4 v1 = *(const float4*)&w[(size_t)dd * IC_ + k0 + kk + 4];
            Bs[kk + 0][dd] = v0.x; Bs[kk + 1][dd] = v0.y;
            Bs[kk + 2][dd] = v0.z; Bs[kk + 3][dd] = v0.w;
            Bs[kk + 4][dd] = v1.x; Bs[kk + 5][dd] = v1.y;
            Bs[kk + 6][dd] = v1.z; Bs[kk + 7][dd] = v1.w;
        }
        __syncthreads();
#pragma unroll
        for (int kk = 0; kk < 16; kk++) {
            float a[4], bb[8];
#pragma unroll
            for (int i = 0; i < 4; i++) a[i] = As[kk][ty * 4 + i];
#pragma unroll
            for (int j = 0; j < 8; j++) bb[j] = Bs[kk][tx * 8 + j];
#pragma unroll
            for (int i = 0; i < 4; i++)
#pragma unroll
                for (int j = 0; j < 8; j++) acc[i][j] += a[i] * bb[j];
        }
        __syncthreads();
    }
#pragma unroll
    for (int i = 0; i < 4; i++) {
        int n = n0 + ty * 4 + i;
#pragma unroll
        for (int j = 0; j < 8; j++) {
            int d = tx * 8 + j;
            R[(size_t)n * PC_ + d] = acc[i][j] + bias[d];
        }
    }
}

// ---------------- kernel 3: P = exp(scale * rp @ ri^T), + row/col sums -------
// Split-tf32 (hi/lo) mma for fp32-grade accuracy. Block 256 thr (8 warps),
// tile 128x128, warp tile 64x32, BK=16.
__global__ __launch_bounds__(256, 2) void k_s() {
    const int b  = blockIdx.z;
    const int i0 = blockIdx.y * 128;
    const int j0 = blockIdx.x * 128;
    const float* A  = g_rp + (size_t)b * N_ * PC_;
    const float* Bm = g_ri + (size_t)b * N_ * PC_;
    float*       Pp = g_S  + (size_t)b * N_ * N_;

    __shared__ float As[16][LDM];
    __shared__ float Bs[16][LDM];
    __shared__ float shr[128], shc[128];

    const int tid  = threadIdx.x;
    const int lane = tid & 31, wid = tid >> 5;
    const int wm = wid & 1, wn = wid >> 1;        // 2 x 4 warps
    const int g = lane >> 2, t = lane & 3;

    float acc[4][4][4];
#pragma unroll
    for (int mf = 0; mf < 4; mf++)
#pragma unroll
        for (int nf = 0; nf < 4; nf++)
#pragma unroll
            for (int q = 0; q < 4; q++) acc[mf][nf][q] = 0.f;

    for (int k0 = 0; k0 < PC_; k0 += 16) {
#pragma unroll
        for (int r = 0; r < 2; r++) {               // transposed fills
            int idx = tid + r * 256;                // 512 float4s each
            int i = idx >> 2, c = (idx & 3) * 4;
            float4 v = *(const float4*)&A[(size_t)(i0 + i) * PC_ + k0 + c];
            As[c + 0][i] = v.x; As[c + 1][i] = v.y;
            As[c + 2][i] = v.z; As[c + 3][i] = v.w;
            float4 u = *(const float4*)&Bm[(size_t)(j0 + i) * PC_ + k0 + c];
            Bs[c + 0][i] = u.x; Bs[c + 1][i] = u.y;
            Bs[c + 2][i] = u.z; Bs[c + 3][i] = u.w;
        }
        __syncthreads();
#pragma unroll
        for (int kk = 0; kk < 16; kk += 8) {
            unsigned ah[4][4], al[4][4], bh[4][2], bl[4][2];
#pragma unroll
            for (int mf = 0; mf < 4; mf++) {
                int m = wm * 64 + mf * 16 + g;
                float x0 = As[kk + t][m],     x1 = As[kk + t][m + 8];
                float x2 = As[kk + t + 4][m], x3 = As[kk + t + 4][m + 8];
                ah[mf][0] = tf32_of(x0); al[mf][0] = tf32_of(x0 - __uint_as_float(ah[mf][0]));
                ah[mf][1] = tf32_of(x1); al[mf][1] = tf32_of(x1 - __uint_as_float(ah[mf][1]));
                ah[mf][2] = tf32_of(x2); al[mf][2] = tf32_of(x2 - __uint_as_float(ah[mf][2]));
                ah[mf][3] = tf32_of(x3); al[mf][3] = tf32_of(x3 - __uint_as_float(ah[mf][3]));
            }
#pragma unroll
            for (int nf = 0; nf < 4; nf++) {
                int n = wn * 32 + nf * 8 + g;
                float y0 = Bs[kk + t][n], y1 = Bs[kk + t + 4][n];
                bh[nf][0] = tf32_of(y0); bl[nf][0] = tf32_of(y0 - __uint_as_float(bh[nf][0]));
                bh[nf][1] = tf32_of(y1); bl[nf][1] = tf32_of(y1 - __uint_as_float(bh[nf][1]));
            }
#pragma unroll
            for (int mf = 0; mf < 4; mf++)
#pragma unroll
                for (int nf = 0; nf < 4; nf++) {
                    mma_tf32(acc[mf][nf], ah[mf][0], ah[mf][1], ah[mf][2], ah[mf][3],
                             bh[nf][0], bh[nf][1]);
                    mma_tf32(acc[mf][nf], ah[mf][0], ah[mf][1], ah[mf][2], ah[mf][3],
                             bl[nf][0], bl[nf][1]);
                    mma_tf32(acc[mf][nf], al[mf][0], al[mf][1], al[mf][2], al[mf][3],
                             bh[nf][0], bh[nf][1]);
                }
        }
        __syncthreads();
    }

    // epilogue: P = exp(scale*acc), store, reduce row/col sums
    if (tid < 128) { shr[tid] = 0.f; shc[tid] = 0.f; }
    __syncthreads();

    float rs[4][2] = {{0.f,0.f},{0.f,0.f},{0.f,0.f},{0.f,0.f}};
    float cs[4][2] = {{0.f,0.f},{0.f,0.f},{0.f,0.f},{0.f,0.f}};
#pragma unroll
    for (int mf = 0; mf < 4; mf++) {
        int row = i0 + wm * 64 + mf * 16 + g;
#pragma unroll
        for (int nf = 0; nf < 4; nf++) {
            int col = j0 + wn * 32 + nf * 8 + 2 * t;
            float p0 = __expf(acc[mf][nf][0] * SCALE_);
            float p1 = __expf(acc[mf][nf][1] * SCALE_);
            float p2 = __expf(acc[mf][nf][2] * SCALE_);
            float p3 = __expf(acc[mf][nf][3] * SCALE_);
            *(float2*)&Pp[(size_t)row * N_ + col]       = make_float2(p0, p1);
            *(float2*)&Pp[(size_t)(row + 8) * N_ + col] = make_float2(p2, p3);
            rs[mf][0] += p0 + p1; rs[mf][1] += p2 + p3;
            cs[nf][0] += p0 + p2; cs[nf][1] += p1 + p3;
        }
    }
    // row sums: reduce over t (lanes differing in bits 0,1)
#pragma unroll
    for (int mf = 0; mf < 4; mf++)
#pragma unroll
        for (int h = 0; h < 2; h++) {
            float v = rs[mf][h];
            v += __shfl_xor_sync(0xffffffffu, v, 1);
            v += __shfl_xor_sync(0xffffffffu, v, 2);
            if (t == 0) atomicAdd(&shr[wm * 64 + mf * 16 + h * 8 + g], v);
        }
    // col sums: reduce over g (lanes differing in bits 2,3,4)
#pragma unroll
    for (int nf = 0; nf < 4; nf++)
#pragma unroll
        for (int q = 0; q < 2; q++) {
            float v = cs[nf][q];
            v += __shfl_xor_sync(0xffffffffu, v, 4);
            v += __shfl_xor_sync(0xffffffffu, v, 8);
            v += __shfl_xor_sync(0xffffffffu, v, 16);
            if (g == 0) atomicAdd(&shc[wn * 32 + nf * 8 + 2 * t + q], v);
        }
    __syncthreads();
    if (tid < 128) {
        atomicAdd(&g_rsum[b * N_ + i0 + tid], shr[tid]);
        atomicAdd(&g_csum[b * N_ + j0 + tid], shc[tid]);
    }
}

// ---------------- kernel 4: AV GEMMs (tf32 single-pass) ----------------------
// mode 0: out_p[i,d] = sum_j P[i,j]          * (rp[j,d]/csum[j])
// mode 1: out_i[i,d] = sum_j P[j,i]          * (ri[j,d]/rsum[j])
// Block 256 thr, tile 128(i) x 128(d), warp 64x32, BK=16, K=4096.
__global__ __launch_bounds__(256, 2) void k_av() {
    const int mode = blockIdx.x;
    const int b    = blockIdx.z;
    const int i0   = blockIdx.y * 128;
    const float* Pp  = g_S + (size_t)b * N_ * N_;
    const float* V   = (mode == 0 ? g_rp : g_ri) + (size_t)b * N_ * PC_;
    const float* sum = (mode == 0 ? g_csum : g_rsum) + b * N_;
    float*       D   = (mode == 0 ? g_outp : g_outi) + (size_t)b * N_ * PC_;

    __shared__ float As[16][LDM];
    __shared__ float Bs[16][LDM];

    const int tid  = threadIdx.x;
    const int lane = tid & 31, wid = tid >> 5;
    const int wm = wid & 1, wn = wid >> 1;
    const int g = lane >> 2, t = lane & 3;

    float acc[4][4][4];
#pragma unroll
    for (int mf = 0; mf < 4; mf++)
#pragma unroll
        for (int nf = 0; nf < 4; nf++)
#pragma unroll
            for (int q = 0; q < 4; q++) acc[mf][nf][q] = 0.f;

    for (int k0 = 0; k0 < N_; k0 += 16) {
        if (mode == 0) {      // As[k][i] = P[(i0+i)*N + k0+k]  (transposed fill)
#pragma unroll
            for (int r = 0; r < 2; r++) {
                int idx = tid + r * 256;
                int i = idx >> 2, c = (idx & 3) * 4;
                float4 v = *(const float4*)&Pp[(size_t)(i0 + i) * N_ + k0 + c];
                As[c + 0][i] = v.x; As[c + 1][i] = v.y;
                As[c + 2][i] = v.z; As[c + 3][i] = v.w;
            }
        } else {              // As[k][i] = P[(k0+k)*N + i0+i]  (direct fill)
#pragma unroll
            for (int r = 0; r < 2; r++) {
                int idx = tid + r * 256;
                int k = idx >> 5, ic = (idx & 31) * 4;
                float4 v = *(const float4*)&Pp[(size_t)(k0 + k) * N_ + i0 + ic];
                *(float4*)&As[k][ic] = v;
            }
        }
        {                     // Bs[k][d] = V[(k0+k)*128 + d] / sum[k0+k]
#pragma unroll
            for (int r = 0; r < 2; r++) {
                int idx = tid + r * 256;
                int k = idx >> 5, dc = (idx & 31) * 4;
                float inv = __fdividef(1.0f, sum[k0 + k]);
                float4 v = *(const float4*)&V[(size_t)(k0 + k) * PC_ + dc];
                v.x *= inv; v.y *= inv; v.z *= inv; v.w *= inv;
                *(float4*)&Bs[k][dc] = v;
            }
        }
        __syncthreads();
#pragma unroll
        for (int kk = 0; kk < 16; kk += 8) {
            unsigned a[4][4], bb[4][2];
#pragma unroll
            for (int mf = 0; mf < 4; mf++) {
                int m = wm * 64 + mf * 16 + g;
                a[mf][0] = tf32_of(As[kk + t][m]);
                a[mf][1] = tf32_of(As[kk + t][m + 8]);
                a[mf][2] = tf32_of(As[kk + t + 4][m]);
                a[mf][3] = tf32_of(As[kk + t + 4][m + 8]);
            }
#pragma unroll
            for (int nf = 0; nf < 4; nf++) {
                int n = wn * 32 + nf * 8 + g;
                bb[nf][0] = tf32_of(Bs[kk + t][n]);
                bb[nf][1] = tf32_of(Bs[kk + t + 4][n]);
            }
#pragma unroll
            for (int mf = 0; mf < 4; mf++)
#pragma unroll
                for (int nf = 0; nf < 4; nf++)
                    mma_tf32(acc[mf][nf], a[mf][0], a[mf][1], a[mf][2], a[mf][3],
                             bb[nf][0], bb[nf][1]);
        }
        __syncthreads();
    }
#pragma unroll
    for (int mf = 0; mf < 4; mf++) {
        int row = i0 + wm * 64 + mf * 16 + g;
#pragma unroll
        for (int nf = 0; nf < 4; nf++) {
            int col = wn * 32 + nf * 8 + 2 * t;
            *(float2*)&D[(size_t)row * PC_ + col]       = make_float2(acc[mf][nf][0], acc[mf][nf][1]);
            *(float2*)&D[(size_t)(row + 8) * PC_ + col] = make_float2(acc[mf][nf][2], acc[mf][nf][3]);
        }
    }
}

// ---------------- kernel 5: conv1d(k=1) + BN(eval) + ReLU --------------------
__global__ void k_conv(const float* __restrict__ w,     const float* __restrict__ cb,
                       const float* __restrict__ gamma, const float* __restrict__ beta,
                       const float* __restrict__ mean,  const float* __restrict__ var,
                       float* __restrict__ out) {
    const int b  = blockIdx.z;
    const int n0 = blockIdx.x * 64;
    const float* P = g_outp + (size_t)b * N_ * PC_;
    const float* I = g_outi + (size_t)b * N_ * PC_;
    __shared__ float As[16][128];
    __shared__ float Bs[16][64];
    const int tx = threadIdx.x, ty = threadIdx.y;
    const int tid = ty * 16 + tx;
    float acc[8][4];
#pragma unroll
    for (int i = 0; i < 8; i++)
#pragma unroll
        for (int j = 0; j < 4; j++) acc[i][j] = 0.f;

    for (int k0 = 0; k0 < 2 * PC_; k0 += 16) {
        {
            int l = tid * 8, oo = l / 16, kk = l % 16;
            float4 v0 = *(const float4*)&w[(size_t)oo * (2 * PC_) + k0 + kk];
            float4 v1 = *(const float4*)&w[(size_t)oo * (2 * PC_) + k0 + kk + 4];
            As[kk + 0][oo] = v0.x; As[kk + 1][oo] = v0.y;
            As[kk + 2][oo] = v0.z; As[kk + 3][oo] = v0.w;
            As[kk + 4][oo] = v1.x; As[kk + 5][oo] = v1.y;
            As[kk + 6][oo] = v1.z; As[kk + 7][oo] = v1.w;
        }
        {
            int l = tid * 4, nn = l / 16, kk = l % 16;
            const float* src = (k0 < PC_) ? &P[(size_t)(n0 + nn) * PC_ + k0 + kk]
                                          : &I[(size_t)(n0 + nn) * PC_ + k0 - PC_ + kk];
            float4 v = *(const float4*)src;
            Bs[kk + 0][nn] = v.x; Bs[kk + 1][nn] = v.y;
            Bs[kk + 2][nn] = v.z; Bs[kk + 3][nn] = v.w;
        }
        __syncthreads();
#pragma unroll
        for (int kk = 0; kk < 16; kk++) {
            float a[8], bb[4];
#pragma unroll
            for (int i = 0; i < 8; i++) a[i] = As[kk][ty * 8 + i];
#pragma unroll
            for (int j = 0; j < 4; j++) bb[j] = Bs[kk][tx * 4 + j];
#pragma unroll
            for (int i = 0; i < 8; i++)
#pragma unroll
                for (int j = 0; j < 4; j++) acc[i][j] += a[i] * bb[j];
        }
        __syncthreads();
    }
#pragma unroll
    for (int i = 0; i < 8; i++) {
        int o = ty * 8 + i;
        float gm   = gamma[o] * rsqrtf(var[o] + 1e-5f);
        float base = gm * (cb[o] - mean[o]) + beta[o];
        float4 v;
        v.x = fmaxf(gm * acc[i][0] + base, 0.f);
        v.y = fmaxf(gm * acc[i][1] + base, 0.f);
        v.z = fmaxf(gm * acc[i][2] + base, 0.f);
        v.w = fmaxf(gm * acc[i][3] + base, 0.f);
        *(float4*)&out[(size_t)b * OC_ * N_ + (size_t)o * N_ + n0 + tx * 4] = v;
    }
}

// ---------------- launch -----------------------------------------------------
extern "C" void kernel_launch(void* const* d_in, const int* in_sizes, int n_in,
                              void* d_out, int out_size) {
    const float* pf     = (const float*)d_in[0];
    const float* img    = (const float*)d_in[1];
    const float* fc2_w  = (const float*)d_in[2];
    const float* fc2_b  = (const float*)d_in[3];
    const float* conv_w = (const float*)d_in[4];
    const float* conv_b = (const float*)d_in[5];
    const float* gamma  = (const float*)d_in[6];
    const float* beta   = (const float*)d_in[7];
    const float* mean   = (const float*)d_in[8];
    const float* var    = (const float*)d_in[9];
    float* out = (float*)d_out;

    k_zero     <<<(B_ * N_ + 511) / 512, 512>>>();
    k_transpose<<<dim3(N_ / 32, PC_ / 32, B_), dim3(32, 8)>>>(pf);
    k_ri       <<<dim3(1, N_ / 64, B_),        dim3(16, 16)>>>(img, fc2_w, fc2_b);
    k_s        <<<dim3(N_ / 128, N_ / 128, B_), 256>>>();
    k_av       <<<dim3(2, N_ / 128, B_),        256>>>();
    k_conv     <<<dim3(N_ / 64, 1, B_),        dim3(16, 16)>>>(conv_w, conv_b, gamma, beta,
                                                               mean, var, out);
}